// round 1
// baseline (speedup 1.0000x reference)
#include <cuda_runtime.h>
#include <cstddef>

#define D        128
#define TWO_D    256
#define MAX_NODES 50000

// Scratch: P[n][0:128] = n_f[n] . W_edge[o][0:128]  (src projection)
//          P[n][128:256] = n_f[n] . W_edge[o][128:256] (dst projection)
__device__ float g_P[(size_t)MAX_NODES * TWO_D];

// ---------------------------------------------------------------------------
// Kernel 1: node projection GEMM.
// P[n][j] = sum_k n_f[n][k] * W(j,k)
//   W(j,k) = (j < 128) ? W_edge[j*256 + k] : W_edge[(j-128)*256 + 128 + k]
// Tiling: TM=128 rows, TN=64 cols, K chunked by 32. 256 threads (16x16),
// each thread an 8x4 microtile. Static smem kept under 48 KB.
// ---------------------------------------------------------------------------
__global__ __launch_bounds__(256) void proj_kernel(
    const float* __restrict__ nf,
    const float* __restrict__ We,
    int n_nodes)
{
    __shared__ float As[128][36];   // [row][k_local], pad 4
    __shared__ float Bs[32][68];    // [k_local][j_local], pad 4

    const int t   = threadIdx.x;
    const int tx  = t & 15;         // 16 col-groups (4 cols each)
    const int ty  = t >> 4;         // 16 row-groups (8 rows each)
    const int row0 = blockIdx.x * 128;
    const int j0   = blockIdx.y * 64;
    const int off  = (j0 >= 128) ? 128 : 0;   // which half of W_edge's input dim
    const int jj0  = j0 & 127;                // output row of W_edge within half

    float acc[8][4];
#pragma unroll
    for (int i = 0; i < 8; i++)
#pragma unroll
        for (int j = 0; j < 4; j++) acc[i][j] = 0.f;

    for (int kc = 0; kc < D; kc += 32) {
        // Load A chunk: 128 rows x 32 k = 1024 float4, 4 per thread.
#pragma unroll
        for (int i = 0; i < 4; i++) {
            int idx = t + i * 256;          // 0..1023
            int r   = idx >> 3;             // 8 float4 per row
            int c4  = idx & 7;
            float4 v = make_float4(0.f, 0.f, 0.f, 0.f);
            int gr = row0 + r;
            if (gr < n_nodes)
                v = __ldg((const float4*)(nf + (size_t)gr * D + kc) + c4);
            *(float4*)&As[r][c4 * 4] = v;
        }
        // Load B chunk: 64 j x 32 k. thread: jj = t>>2, k slice of 8 (2 float4).
        {
            int jj    = t >> 2;             // 0..63
            int kbase = (t & 3) * 8;        // 0,8,16,24
            const float* wrow = We + (size_t)(jj0 + jj) * TWO_D + off + kc + kbase;
#pragma unroll
            for (int i = 0; i < 2; i++) {
                float4 v = __ldg((const float4*)(wrow + i * 4));
                int k = kbase + i * 4;
                Bs[k + 0][jj] = v.x;
                Bs[k + 1][jj] = v.y;
                Bs[k + 2][jj] = v.z;
                Bs[k + 3][jj] = v.w;
            }
        }
        __syncthreads();

#pragma unroll
        for (int k = 0; k < 32; k++) {
            float4 b = *(const float4*)&Bs[k][tx * 4];
            float a[8];
#pragma unroll
            for (int i = 0; i < 8; i++) a[i] = As[ty * 8 + i][k];
#pragma unroll
            for (int i = 0; i < 8; i++) {
                acc[i][0] = fmaf(a[i], b.x, acc[i][0]);
                acc[i][1] = fmaf(a[i], b.y, acc[i][1]);
                acc[i][2] = fmaf(a[i], b.z, acc[i][2]);
                acc[i][3] = fmaf(a[i], b.w, acc[i][3]);
            }
        }
        __syncthreads();
    }

#pragma unroll
    for (int i = 0; i < 8; i++) {
        int gr = row0 + ty * 8 + i;
        if (gr < n_nodes) {
            float4 v = make_float4(acc[i][0], acc[i][1], acc[i][2], acc[i][3]);
            *(float4*)(g_P + (size_t)gr * TWO_D + j0 + tx * 4) = v;
        }
    }
}

// ---------------------------------------------------------------------------
// Kernel 2: per-edge apply. One warp per edge, one float4 per lane.
// e_feat[e] = relu(P[src][0:128] + P[dst][128:256])
// a[e]      = leaky_relu(dot(e_feat[e], w_attn), 0.01)
// Streaming stores (__stcs) keep the 516 MB output stream from evicting the
// L2-resident P table (51 MB).
// ---------------------------------------------------------------------------
__global__ __launch_bounds__(256) void edge_kernel(
    const int* __restrict__ src,
    const int* __restrict__ dst,
    const float* __restrict__ w_attn,
    float* __restrict__ e_out,
    float* __restrict__ a_out,
    int n_edges)
{
    int gw   = (int)((blockIdx.x * (unsigned)blockDim.x + threadIdx.x) >> 5);
    int lane = threadIdx.x & 31;
    if (gw >= n_edges) return;

    int s = __ldg(src + gw);
    int d = __ldg(dst + gw);

    float4 a = __ldg((const float4*)(g_P + (size_t)s * TWO_D) + lane);
    float4 b = __ldg((const float4*)(g_P + (size_t)d * TWO_D + D) + lane);
    float4 w = __ldg((const float4*)w_attn + lane);

    float4 r;
    r.x = fmaxf(a.x + b.x, 0.f);
    r.y = fmaxf(a.y + b.y, 0.f);
    r.z = fmaxf(a.z + b.z, 0.f);
    r.w = fmaxf(a.w + b.w, 0.f);

    __stcs((float4*)(e_out + (size_t)gw * D) + lane, r);

    float dot = r.x * w.x + r.y * w.y + r.z * w.z + r.w * w.w;
#pragma unroll
    for (int o = 16; o; o >>= 1)
        dot += __shfl_xor_sync(0xffffffffu, dot, o);

    if (lane == 0)
        __stcs(a_out + gw, dot > 0.f ? dot : 0.01f * dot);
}

// ---------------------------------------------------------------------------
// Launch. Inputs (metadata order): n_f [N*128] f32, src_idx [E] i32,
// dst_idx [E] i32, W_edge [128*256] f32, W_attn [128] f32.
// Output: [e_feat (E*128) | a_fact (E)] f32.
// ---------------------------------------------------------------------------
extern "C" void kernel_launch(void* const* d_in, const int* in_sizes, int n_in,
                              void* d_out, int out_size)
{
    const float* nf  = (const float*)d_in[0];
    const int*   src = (const int*)d_in[1];
    const int*   dst = (const int*)d_in[2];
    const float* We  = (const float*)d_in[3];
    const float* Wa  = (const float*)d_in[4];

    int n_nodes = in_sizes[0] / D;
    if (n_nodes > MAX_NODES) n_nodes = MAX_NODES;
    int n_edges = in_sizes[1];

    float* e_out = (float*)d_out;
    float* a_out = e_out + (size_t)n_edges * D;

    dim3 pgrid((n_nodes + 127) / 128, TWO_D / 64);
    proj_kernel<<<pgrid, 256>>>(nf, We, n_nodes);

    long long total_threads = (long long)n_edges * 32;
    int blocks = (int)((total_threads + 255) / 256);
    edge_kernel<<<blocks, 256>>>(src, dst, Wa, e_out, a_out, n_edges);
}

// round 4
// speedup vs baseline: 1.3237x; 1.3237x over previous
#include <cuda_runtime.h>
#include <cstddef>

#define D        128
#define TWO_D    256
#define MAX_NODES 50000

// Scratch: P[n][0:128] = src projection, P[n][128:256] = dst projection.
__device__ float g_P[(size_t)MAX_NODES * TWO_D];

// ---------------------------------------------------------------------------
// Kernel 1: node projection GEMM.  P[n][off+j] = sum_k n_f[n][k] * We[j][off+k]
// blockIdx.y selects half (off = 0 or 128). TM=128, TN=128, K chunk 32.
// 256 threads, 8x8 microtile per thread. A and B both stored k-major in smem
// so the inner loop is 4x LDS.128 per k. Row/col ownership split into
// {q*4..q*4+4} U {64+q*4..} so LDS.128 phases are bank-conflict-free.
// ---------------------------------------------------------------------------
__global__ __launch_bounds__(256) void proj_kernel(
    const float* __restrict__ nf,
    const float* __restrict__ We,
    int n_nodes)
{
    __shared__ float As[32][132];   // [k_local][row], pad 4
    __shared__ float Bs[32][132];   // [k_local][col], pad 4

    const int t    = threadIdx.x;
    const int tx   = t & 15;        // col group
    const int ty   = t >> 4;        // row group
    const int row0 = blockIdx.x * 128;
    const int off  = blockIdx.y * D;     // 0: src half, 128: dst half

    float acc[8][8];
#pragma unroll
    for (int i = 0; i < 8; i++)
#pragma unroll
        for (int j = 0; j < 8; j++) acc[i][j] = 0.f;

    for (int kc = 0; kc < D; kc += 32) {
        // A chunk: 128 rows x 32 k, transposed into As[k][row].
#pragma unroll
        for (int i = 0; i < 4; i++) {
            int idx = t + i * 256;      // 0..1023
            int r   = idx >> 3;
            int c4  = idx & 7;
            float4 v = make_float4(0.f, 0.f, 0.f, 0.f);
            int gr = row0 + r;
            if (gr < n_nodes)
                v = __ldg((const float4*)(nf + (size_t)gr * D + kc) + c4);
            int k = c4 * 4;
            As[k + 0][r] = v.x;
            As[k + 1][r] = v.y;
            As[k + 2][r] = v.z;
            As[k + 3][r] = v.w;
        }
        // B chunk: 128 cols (output features j) x 32 k, transposed into Bs[k][j].
#pragma unroll
        for (int i = 0; i < 4; i++) {
            int idx = t + i * 256;
            int j   = idx >> 3;
            int c4  = idx & 7;
            float4 v = __ldg((const float4*)(We + (size_t)j * TWO_D + off + kc) + c4);
            int k = c4 * 4;
            Bs[k + 0][j] = v.x;
            Bs[k + 1][j] = v.y;
            Bs[k + 2][j] = v.z;
            Bs[k + 3][j] = v.w;
        }
        __syncthreads();

#pragma unroll
        for (int k = 0; k < 32; k++) {
            float av[8], bv[8];
            *(float4*)&av[0] = *(const float4*)&As[k][ty * 4];
            *(float4*)&av[4] = *(const float4*)&As[k][64 + ty * 4];
            *(float4*)&bv[0] = *(const float4*)&Bs[k][tx * 4];
            *(float4*)&bv[4] = *(const float4*)&Bs[k][64 + tx * 4];
#pragma unroll
            for (int i = 0; i < 8; i++)
#pragma unroll
                for (int j = 0; j < 8; j++)
                    acc[i][j] = fmaf(av[i], bv[j], acc[i][j]);
        }
        __syncthreads();
    }

    // Store: rows {row0+ty*4+i} and {row0+64+ty*4+i}, cols off+tx*4 / off+64+tx*4.
#pragma unroll
    for (int half = 0; half < 2; half++) {
#pragma unroll
        for (int i = 0; i < 4; i++) {
            int gr = row0 + half * 64 + ty * 4 + i;
            if (gr < n_nodes) {
                int ai = half * 4 + i;
                float* p = g_P + (size_t)gr * TWO_D + off;
                *(float4*)(p + tx * 4) =
                    make_float4(acc[ai][0], acc[ai][1], acc[ai][2], acc[ai][3]);
                *(float4*)(p + 64 + tx * 4) =
                    make_float4(acc[ai][4], acc[ai][5], acc[ai][6], acc[ai][7]);
            }
        }
    }
}

// ---------------------------------------------------------------------------
// Kernel 2: per-edge apply, 4 edges per warp for 8 outstanding 16B gathers
// per thread (MLP). One float4 per lane per edge. Streaming stores keep the
// 516 MB output stream from evicting the 51 MB L2-resident P table.
// ---------------------------------------------------------------------------
__global__ __launch_bounds__(256) void edge_kernel(
    const int* __restrict__ src,
    const int* __restrict__ dst,
    const float* __restrict__ w_attn,
    float* __restrict__ e_out,
    float* __restrict__ a_out,
    int n_edges)
{
    const int lane = threadIdx.x & 31;
    const int warp = (int)((blockIdx.x * (unsigned)blockDim.x + threadIdx.x) >> 5);
    const int e0   = warp * 4;
    if (e0 >= n_edges) return;
    const int ne = min(4, n_edges - e0);

    // w first so all loads below batch into one MLP group.
    float4 w = __ldg((const float4*)w_attn + lane);

    int s[4], d[4];
#pragma unroll
    for (int i = 0; i < 4; i++) {
        int e = e0 + ((i < ne) ? i : 0);
        s[i] = __ldg(src + e);
        d[i] = __ldg(dst + e);
    }

    float4 a[4], b[4];
#pragma unroll
    for (int i = 0; i < 4; i++) {
        a[i] = __ldg((const float4*)(g_P + (size_t)s[i] * TWO_D) + lane);
        b[i] = __ldg((const float4*)(g_P + (size_t)d[i] * TWO_D + D) + lane);
    }

    float dot[4];
#pragma unroll
    for (int i = 0; i < 4; i++) {
        float4 r;
        r.x = fmaxf(a[i].x + b[i].x, 0.f);
        r.y = fmaxf(a[i].y + b[i].y, 0.f);
        r.z = fmaxf(a[i].z + b[i].z, 0.f);
        r.w = fmaxf(a[i].w + b[i].w, 0.f);
        if (i < ne)
            __stcs((float4*)(e_out + (size_t)(e0 + i) * D) + lane, r);
        dot[i] = r.x * w.x + r.y * w.y + r.z * w.z + r.w * w.w;
    }

    // Four independent butterfly chains, interleaved for ILP.
#pragma unroll
    for (int o = 16; o; o >>= 1) {
        dot[0] += __shfl_xor_sync(0xffffffffu, dot[0], o);
        dot[1] += __shfl_xor_sync(0xffffffffu, dot[1], o);
        dot[2] += __shfl_xor_sync(0xffffffffu, dot[2], o);
        dot[3] += __shfl_xor_sync(0xffffffffu, dot[3], o);
    }

    // All lanes hold all four dots; lanes 0..ne-1 write coalesced.
    float v = dot[0];
    if (lane == 1) v = dot[1];
    if (lane == 2) v = dot[2];
    if (lane == 3) v = dot[3];
    if (lane < ne) {
        v = v > 0.f ? v : 0.01f * v;
        __stcs(a_out + e0 + lane, v);
    }
}

// ---------------------------------------------------------------------------
// Launch. Inputs: n_f [N*128] f32, src_idx [E] i32, dst_idx [E] i32,
// W_edge [128*256] f32, W_attn [128] f32. Output: [e_feat E*128 | a_fact E].
// ---------------------------------------------------------------------------
extern "C" void kernel_launch(void* const* d_in, const int* in_sizes, int n_in,
                              void* d_out, int out_size)
{
    const float* nf  = (const float*)d_in[0];
    const int*   src = (const int*)d_in[1];
    const int*   dst = (const int*)d_in[2];
    const float* We  = (const float*)d_in[3];
    const float* Wa  = (const float*)d_in[4];

    int n_nodes = in_sizes[0] / D;
    if (n_nodes > MAX_NODES) n_nodes = MAX_NODES;
    int n_edges = in_sizes[1];

    float* e_out = (float*)d_out;
    float* a_out = e_out + (size_t)n_edges * D;

    dim3 pgrid((n_nodes + 127) / 128, 2);
    proj_kernel<<<pgrid, 256>>>(nf, We, n_nodes);

    int warps  = (n_edges + 3) / 4;
    int blocks = (warps * 32 + 255) / 256;
    edge_kernel<<<blocks, 256>>>(src, dst, Wa, e_out, a_out, n_edges);
}